// round 13
// baseline (speedup 1.0000x reference)
#include <cuda_runtime.h>
#include <cuda_bf16.h>
#include <cstdint>

#define NN 50000
#define NE 800000
#define NG 256
#define FIN 256
#define HD 64

__device__ float g_q[NN * HD];
__device__ float g_k[NN * HD];
__device__ float g_v[NN * HD];
__device__ float g_ex[NE];
__device__ float g_den[NG];
// W transposed: [n=192][k=256], bf16 hi/lo split
__device__ __nv_bfloat16 g_wth[192 * 256];
__device__ __nv_bfloat16 g_wtl[192 * 256];

// smem layout (dynamic): A hi/lo [64][64] bf16, B hi/lo [192][64] bf16
#define SMA_HI 0
#define SMA_LO 8192
#define SMB_HI 16384
#define SMB_LO (16384 + 24576)
#define SM_TOT (16384 + 49152)   // 64 KB

__device__ __forceinline__ uint32_t smem_u32(const void* p) {
    uint32_t a;
    asm("{ .reg .u64 t; cvta.to.shared.u64 t, %1; cvt.u32.u64 %0, t; }"
        : "=r"(a) : "l"(p));
    return a;
}
__device__ __forceinline__ uint32_t swz(uint32_t row, uint32_t kb) {
    return (row * 128 + kb * 16) ^ ((row & 7) << 4);
}
__device__ __forceinline__ void ldsm_x4(uint32_t* r, uint32_t addr) {
    asm volatile("ldmatrix.sync.aligned.m8n8.x4.shared.b16 {%0,%1,%2,%3}, [%4];"
                 : "=r"(r[0]), "=r"(r[1]), "=r"(r[2]), "=r"(r[3]) : "r"(addr));
}
__device__ __forceinline__ void mma_bf16(float* c, const uint32_t* a,
                                         const uint32_t* b) {
    asm volatile(
        "mma.sync.aligned.m16n8k16.row.col.f32.bf16.bf16.f32 "
        "{%0,%1,%2,%3}, {%4,%5,%6,%7}, {%8,%9}, {%0,%1,%2,%3};"
        : "+f"(c[0]), "+f"(c[1]), "+f"(c[2]), "+f"(c[3])
        : "r"(a[0]), "r"(a[1]), "r"(a[2]), "r"(a[3]), "r"(b[0]), "r"(b[1]));
}
__device__ __forceinline__ uint32_t pack_bf2(float x, float y) {
    __nv_bfloat162 h = {__float2bfloat16(x), __float2bfloat16(y)};
    return *(uint32_t*)&h;
}

// ---------------------------------------------------------------------------
// W pre-transpose hi+lo. Block 0 also zeroes g_den.
// ---------------------------------------------------------------------------
__global__ __launch_bounds__(256) void wt_build(
    const float* __restrict__ Wq, const float* __restrict__ Wk,
    const float* __restrict__ Wv)
{
    int n = blockIdx.x;               // 0..191
    int k = threadIdx.x;              // 0..255
    if (n == 0) g_den[k] = 0.f;
    const float* W = (n < 64) ? Wq : (n < 128 ? Wk : Wv);
    float w = W[(size_t)k * HD + (n & 63)];
    __nv_bfloat16 h = __float2bfloat16(w);
    g_wth[n * FIN + k] = h;
    g_wtl[n * FIN + k] = __float2bfloat16(w - __bfloat162float(h));
}

// ---------------------------------------------------------------------------
// Fused QKV GEMM on HMMA bf16x3 (R11 best config). BM=64, 256 threads /
// 8 warps (2M x 4N), 2 CTAs per SM. Per warp: 32 rows x 48 cols.
// K chunked by 64 (4 chunks).
// ---------------------------------------------------------------------------
__global__ __launch_bounds__(256, 2) void qkv_gemm_hmma(
    const float* __restrict__ x,
    const float* __restrict__ bq, const float* __restrict__ bk,
    const float* __restrict__ bv)
{
    extern __shared__ char smem[];
    const uint32_t sb = smem_u32(smem);
    const int tid = threadIdx.x;
    const int wid = tid >> 5;
    const int lane = tid & 31;
    const int m_warp = wid & 1;       // 2 M groups of 32 rows
    const int n_warp = wid >> 1;      // 4 N groups of 48 cols
    const int row0 = blockIdx.x * 64;

    float acc[2][6][4];
#pragma unroll
    for (int i = 0; i < 2; i++)
#pragma unroll
        for (int j = 0; j < 6; j++)
#pragma unroll
            for (int t = 0; t < 4; t++) acc[i][j][t] = 0.f;

    const int lm_r = lane & 15;
    const int lm_h = lane >> 4;

    for (int c = 0; c < 4; c++) {
        __syncthreads();
        // ---- stage A: x[row0:+64, c*64:+64] -> bf16 hi/lo swizzled ----
#pragma unroll
        for (int it = 0; it < 2; it++) {
            int idx = tid + it * 256;         // 512 (row,kb) pairs
            int r  = idx >> 3;
            int kb = idx & 7;
            int grow = row0 + r;
            float4 f0 = make_float4(0.f, 0.f, 0.f, 0.f), f1 = f0;
            if (grow < NN) {
                const float* src = &x[(size_t)grow * FIN + c * 64 + kb * 8];
                f0 = *(const float4*)src;
                f1 = *(const float4*)(src + 4);
            }
            float fv[8] = {f0.x, f0.y, f0.z, f0.w, f1.x, f1.y, f1.z, f1.w};
            uint32_t hi[4], lo[4];
#pragma unroll
            for (int j = 0; j < 4; j++) {
                float a = fv[j * 2], b = fv[j * 2 + 1];
                __nv_bfloat16 ha = __float2bfloat16(a);
                __nv_bfloat16 hb = __float2bfloat16(b);
                hi[j] = pack_bf2(a, b);
                lo[j] = pack_bf2(a - __bfloat162float(ha),
                                 b - __bfloat162float(hb));
            }
            uint32_t off = swz(r, kb);
            *(uint4*)(smem + SMA_HI + off) = make_uint4(hi[0], hi[1], hi[2], hi[3]);
            *(uint4*)(smem + SMA_LO + off) = make_uint4(lo[0], lo[1], lo[2], lo[3]);
        }
        // ---- stage B: Wt[0:192, c*64:+64] hi/lo -> swizzled smem copy ----
#pragma unroll
        for (int it = 0; it < 6; it++) {
            int idx = tid + it * 256;         // 1536 (n,kb) pairs
            int n  = idx >> 3;
            int kb = idx & 7;
            uint32_t off = swz(n, kb);
            *(uint4*)(smem + SMB_HI + off) =
                *(const uint4*)&g_wth[n * FIN + c * 64 + kb * 8];
            *(uint4*)(smem + SMB_LO + off) =
                *(const uint4*)&g_wtl[n * FIN + c * 64 + kb * 8];
        }
        __syncthreads();

        // ---- compute: 4 k-steps of k16 ----
#pragma unroll
        for (int ks = 0; ks < 4; ks++) {
            uint32_t ah[2][4], al[2][4];
#pragma unroll
            for (int mt = 0; mt < 2; mt++) {
                int r = m_warp * 32 + mt * 16 + lm_r;
                uint32_t o = swz(r, ks * 2 + lm_h);
                ldsm_x4(ah[mt], sb + SMA_HI + o);
                ldsm_x4(al[mt], sb + SMA_LO + o);
            }
#pragma unroll
            for (int p = 0; p < 3; p++) {     // pairs of n-tiles
                int n = n_warp * 48 + p * 16 + lm_r;
                uint32_t o = swz(n, ks * 2 + lm_h);
                uint32_t th[4], tl[4];
                ldsm_x4(th, sb + SMB_HI + o);
                ldsm_x4(tl, sb + SMB_LO + o);
                uint32_t bh0[2] = {th[0], th[2]}, bh1[2] = {th[1], th[3]};
                uint32_t bl0[2] = {tl[0], tl[2]}, bl1[2] = {tl[1], tl[3]};
#pragma unroll
                for (int mt = 0; mt < 2; mt++) {
                    mma_bf16(acc[mt][p * 2], ah[mt], bh0);
                    mma_bf16(acc[mt][p * 2], ah[mt], bl0);
                    mma_bf16(acc[mt][p * 2], al[mt], bh0);
                    mma_bf16(acc[mt][p * 2 + 1], ah[mt], bh1);
                    mma_bf16(acc[mt][p * 2 + 1], ah[mt], bl1);
                    mma_bf16(acc[mt][p * 2 + 1], al[mt], bh1);
                }
            }
        }
    }

    // ---- epilogue ----
    const float* biases[3] = {bq, bk, bv};
    float* outs[3] = {g_q, g_k, g_v};
    const int r0 = lane >> 2;
    const int cp = (lane & 3) * 2;
#pragma unroll
    for (int mt = 0; mt < 2; mt++) {
        int gr = row0 + m_warp * 32 + mt * 16 + r0;
#pragma unroll
        for (int nt = 0; nt < 6; nt++) {
            int col = n_warp * 48 + nt * 8 + cp;
            int sel = col >> 6;
            int ci  = col & 63;
            float b0 = biases[sel][ci], b1 = biases[sel][ci + 1];
            if (gr < NN) {
                float2 st = make_float2(acc[mt][nt][0] + b0, acc[mt][nt][1] + b1);
                *(float2*)&outs[sel][(size_t)gr * HD + ci] = st;
            }
            if (gr + 8 < NN) {
                float2 st = make_float2(acc[mt][nt][2] + b0, acc[mt][nt][3] + b1);
                *(float2*)&outs[sel][(size_t)(gr + 8) * HD + ci] = st;
            }
        }
    }
}

// ---------------------------------------------------------------------------
// Pass 1: ex[e] = exp(dot(k[src], q[dest]) / 8); denominator via shared bins.
// 4 edges per warp per iteration (8 lanes x 32B each).
// ---------------------------------------------------------------------------
__global__ __launch_bounds__(512) void edge_pass1(
    const int* __restrict__ ei, const int* __restrict__ batch)
{
    __shared__ float sden[NG];
    const int tid = threadIdx.x;
    if (tid < NG) sden[tid] = 0.f;
    __syncthreads();

    const int lane = tid & 31;
    const int sub = lane >> 3;
    const int sl  = lane & 7;
    const int w = blockIdx.x * 16 + (tid >> 5);
    const int stride = gridDim.x * 16 * 4;

    for (int e0 = w * 4; e0 < NE; e0 += stride) {
        int e = e0 + sub;
        float p = 0.f;
        int s = 0;
        if (e < NE) {
            s = __ldg(&ei[e]);
            int d = __ldg(&ei[NE + e]);
            const float* kr = &g_k[s * HD + sl * 8];
            const float* qr = &g_q[d * HD + sl * 8];
            float4 k0 = *(const float4*)kr;
            float4 k1 = *(const float4*)(kr + 4);
            float4 q0 = *(const float4*)qr;
            float4 q1 = *(const float4*)(qr + 4);
            p = k0.x * q0.x + k0.y * q0.y + k0.z * q0.z + k0.w * q0.w
              + k1.x * q1.x + k1.y * q1.y + k1.z * q1.z + k1.w * q1.w;
        }
#pragma unroll
        for (int o = 4; o > 0; o >>= 1)
            p += __shfl_xor_sync(0xffffffffu, p, o);
        if (sl == 0 && e < NE) {
            float ex = __expf(p * 0.125f);
            g_ex[e] = ex;
            atomicAdd(&sden[__ldg(&batch[s])], ex);
        }
    }
    __syncthreads();
    if (tid < NG) {
        float v = sden[tid];
        if (v != 0.f) atomicAdd(&g_den[tid], v);
    }
}

// ---------------------------------------------------------------------------
// Pass 2: out[dest] += v[src] * (ex[e] * rcp(den[batch[src]] + 1e-6)).
// 4 edges per warp (8 lanes x 32B each), 2x red.v4 per lane.
// ---------------------------------------------------------------------------
__global__ __launch_bounds__(256) void edge_pass2(
    const int* __restrict__ ei, const int* __restrict__ batch,
    float* __restrict__ out)
{
    const int lane = threadIdx.x & 31;
    const int sub = lane >> 3;
    const int sl  = lane & 7;
    const int e = (blockIdx.x * 8 + (threadIdx.x >> 5)) * 4 + sub;

    int s = __ldg(&ei[e]);
    int d = __ldg(&ei[NE + e]);

    float a = 0.f;
    if (sl == 0)
        a = g_ex[e] * __frcp_rn(g_den[__ldg(&batch[s])] + 1e-6f);
    a = __shfl_sync(0xffffffffu, a, sub << 3);

    const float* vr = &g_v[s * HD + sl * 8];
    float4 v0 = *(const float4*)vr;
    float4 v1 = *(const float4*)(vr + 4);
    float* dst = &out[d * HD + sl * 8];
    asm volatile("red.global.add.v4.f32 [%0], {%1, %2, %3, %4};"
                 :: "l"(dst), "f"(v0.x * a), "f"(v0.y * a),
                    "f"(v0.z * a), "f"(v0.w * a)
                 : "memory");
    asm volatile("red.global.add.v4.f32 [%0], {%1, %2, %3, %4};"
                 :: "l"(dst + 4), "f"(v1.x * a), "f"(v1.y * a),
                    "f"(v1.z * a), "f"(v1.w * a)
                 : "memory");
}

// ---------------------------------------------------------------------------
extern "C" void kernel_launch(void* const* d_in, const int* in_sizes, int n_in,
                              void* d_out, int out_size)
{
    const float* x     = (const float*)d_in[0];
    const float* Wq    = (const float*)d_in[1];
    const float* bq    = (const float*)d_in[2];
    const float* Wk    = (const float*)d_in[3];
    const float* bk    = (const float*)d_in[4];
    const float* Wv    = (const float*)d_in[5];
    const float* bv    = (const float*)d_in[6];
    const int*   ei    = (const int*)d_in[7];    // int32 (JAX x64 disabled)
    const int*   batch = (const int*)d_in[8];
    float* out = (float*)d_out;

    cudaFuncSetAttribute(qkv_gemm_hmma,
                         cudaFuncAttributeMaxDynamicSharedMemorySize, SM_TOT);

    // Launch order: ncu (-s 5) profiles edge_pass2.
    wt_build<<<192, 256>>>(Wq, Wk, Wv);                            // 1 (+zero g_den)
    cudaMemsetAsync(d_out, 0, (size_t)out_size * sizeof(float));   // 2
    qkv_gemm_hmma<<<(NN + 63) / 64, 256, SM_TOT>>>(x, bq, bk, bv); // 3
    edge_pass1<<<592, 512>>>(ei, batch);                           // 4
    edge_pass2<<<NE / 32, 256>>>(ei, batch, out);                  // 5 <- ncu
}

// round 14
// speedup vs baseline: 1.1237x; 1.1237x over previous
#include <cuda_runtime.h>
#include <cuda_bf16.h>
#include <cstdint>

#define NN 50000
#define NE 800000
#define NG 256
#define FIN 256
#define HD 64

__device__ float g_q[NN * HD];
__device__ float g_k[NN * HD];
__device__ float g_v[NN * HD];
__device__ float g_ex[NE];
__device__ float g_den[NG];
__device__ float g_inv[NN];
// W transposed: [n=192][k=256], bf16 hi/lo split
__device__ __nv_bfloat16 g_wth[192 * 256];
__device__ __nv_bfloat16 g_wtl[192 * 256];

// smem layout (dynamic): A hi/lo [64][64] bf16, B hi/lo [192][64] bf16
#define SMA_HI 0
#define SMA_LO 8192
#define SMB_HI 16384
#define SMB_LO (16384 + 24576)
#define SM_TOT (16384 + 49152)   // 64 KB

__device__ __forceinline__ uint32_t smem_u32(const void* p) {
    uint32_t a;
    asm("{ .reg .u64 t; cvta.to.shared.u64 t, %1; cvt.u32.u64 %0, t; }"
        : "=r"(a) : "l"(p));
    return a;
}
__device__ __forceinline__ uint32_t swz(uint32_t row, uint32_t kb) {
    return (row * 128 + kb * 16) ^ ((row & 7) << 4);
}
__device__ __forceinline__ void ldsm_x4(uint32_t* r, uint32_t addr) {
    asm volatile("ldmatrix.sync.aligned.m8n8.x4.shared.b16 {%0,%1,%2,%3}, [%4];"
                 : "=r"(r[0]), "=r"(r[1]), "=r"(r[2]), "=r"(r[3]) : "r"(addr));
}
__device__ __forceinline__ void mma_bf16(float* c, const uint32_t* a,
                                         const uint32_t* b) {
    asm volatile(
        "mma.sync.aligned.m16n8k16.row.col.f32.bf16.bf16.f32 "
        "{%0,%1,%2,%3}, {%4,%5,%6,%7}, {%8,%9}, {%0,%1,%2,%3};"
        : "+f"(c[0]), "+f"(c[1]), "+f"(c[2]), "+f"(c[3])
        : "r"(a[0]), "r"(a[1]), "r"(a[2]), "r"(a[3]), "r"(b[0]), "r"(b[1]));
}
__device__ __forceinline__ uint32_t pack_bf2(float x, float y) {
    __nv_bfloat162 h = {__float2bfloat16(x), __float2bfloat16(y)};
    return *(uint32_t*)&h;
}

// ---------------------------------------------------------------------------
// W pre-transpose hi+lo (merged). Block 0 also zeroes g_den.
// ---------------------------------------------------------------------------
__global__ __launch_bounds__(256) void wt_build(
    const float* __restrict__ Wq, const float* __restrict__ Wk,
    const float* __restrict__ Wv)
{
    int n = blockIdx.x;               // 0..191
    int k = threadIdx.x;              // 0..255
    if (n == 0) g_den[k] = 0.f;
    const float* W = (n < 64) ? Wq : (n < 128 ? Wk : Wv);
    float w = W[(size_t)k * HD + (n & 63)];
    __nv_bfloat16 h = __float2bfloat16(w);
    g_wth[n * FIN + k] = h;
    g_wtl[n * FIN + k] = __float2bfloat16(w - __bfloat162float(h));
}

// ---------------------------------------------------------------------------
// Fused QKV GEMM on HMMA bf16x3 (R11 best-measured config). BM=64,
// 256 threads / 8 warps (2M x 4N), 2 CTAs per SM. K chunked by 64.
// ---------------------------------------------------------------------------
__global__ __launch_bounds__(256, 2) void qkv_gemm_hmma(
    const float* __restrict__ x,
    const float* __restrict__ bq, const float* __restrict__ bk,
    const float* __restrict__ bv)
{
    extern __shared__ char smem[];
    const uint32_t sb = smem_u32(smem);
    const int tid = threadIdx.x;
    const int wid = tid >> 5;
    const int lane = tid & 31;
    const int m_warp = wid & 1;       // 2 M groups of 32 rows
    const int n_warp = wid >> 1;      // 4 N groups of 48 cols
    const int row0 = blockIdx.x * 64;

    float acc[2][6][4];
#pragma unroll
    for (int i = 0; i < 2; i++)
#pragma unroll
        for (int j = 0; j < 6; j++)
#pragma unroll
            for (int t = 0; t < 4; t++) acc[i][j][t] = 0.f;

    const int lm_r = lane & 15;
    const int lm_h = lane >> 4;

    for (int c = 0; c < 4; c++) {
        __syncthreads();
        // ---- stage A: x[row0:+64, c*64:+64] -> bf16 hi/lo swizzled ----
#pragma unroll
        for (int it = 0; it < 2; it++) {
            int idx = tid + it * 256;         // 512 (row,kb) pairs
            int r  = idx >> 3;
            int kb = idx & 7;
            int grow = row0 + r;
            float4 f0 = make_float4(0.f, 0.f, 0.f, 0.f), f1 = f0;
            if (grow < NN) {
                const float* src = &x[(size_t)grow * FIN + c * 64 + kb * 8];
                f0 = *(const float4*)src;
                f1 = *(const float4*)(src + 4);
            }
            float fv[8] = {f0.x, f0.y, f0.z, f0.w, f1.x, f1.y, f1.z, f1.w};
            uint32_t hi[4], lo[4];
#pragma unroll
            for (int j = 0; j < 4; j++) {
                float a = fv[j * 2], b = fv[j * 2 + 1];
                __nv_bfloat16 ha = __float2bfloat16(a);
                __nv_bfloat16 hb = __float2bfloat16(b);
                hi[j] = pack_bf2(a, b);
                lo[j] = pack_bf2(a - __bfloat162float(ha),
                                 b - __bfloat162float(hb));
            }
            uint32_t off = swz(r, kb);
            *(uint4*)(smem + SMA_HI + off) = make_uint4(hi[0], hi[1], hi[2], hi[3]);
            *(uint4*)(smem + SMA_LO + off) = make_uint4(lo[0], lo[1], lo[2], lo[3]);
        }
        // ---- stage B: Wt[0:192, c*64:+64] hi/lo -> swizzled smem copy ----
#pragma unroll
        for (int it = 0; it < 6; it++) {
            int idx = tid + it * 256;         // 1536 (n,kb) pairs
            int n  = idx >> 3;
            int kb = idx & 7;
            uint32_t off = swz(n, kb);
            *(uint4*)(smem + SMB_HI + off) =
                *(const uint4*)&g_wth[n * FIN + c * 64 + kb * 8];
            *(uint4*)(smem + SMB_LO + off) =
                *(const uint4*)&g_wtl[n * FIN + c * 64 + kb * 8];
        }
        __syncthreads();

        // ---- compute: 4 k-steps of k16 ----
#pragma unroll
        for (int ks = 0; ks < 4; ks++) {
            uint32_t ah[2][4], al[2][4];
#pragma unroll
            for (int mt = 0; mt < 2; mt++) {
                int r = m_warp * 32 + mt * 16 + lm_r;
                uint32_t o = swz(r, ks * 2 + lm_h);
                ldsm_x4(ah[mt], sb + SMA_HI + o);
                ldsm_x4(al[mt], sb + SMA_LO + o);
            }
#pragma unroll
            for (int p = 0; p < 3; p++) {     // pairs of n-tiles
                int n = n_warp * 48 + p * 16 + lm_r;
                uint32_t o = swz(n, ks * 2 + lm_h);
                uint32_t th[4], tl[4];
                ldsm_x4(th, sb + SMB_HI + o);
                ldsm_x4(tl, sb + SMB_LO + o);
                uint32_t bh0[2] = {th[0], th[2]}, bh1[2] = {th[1], th[3]};
                uint32_t bl0[2] = {tl[0], tl[2]}, bl1[2] = {tl[1], tl[3]};
#pragma unroll
                for (int mt = 0; mt < 2; mt++) {
                    mma_bf16(acc[mt][p * 2], ah[mt], bh0);
                    mma_bf16(acc[mt][p * 2], ah[mt], bl0);
                    mma_bf16(acc[mt][p * 2], al[mt], bh0);
                    mma_bf16(acc[mt][p * 2 + 1], ah[mt], bh1);
                    mma_bf16(acc[mt][p * 2 + 1], ah[mt], bl1);
                    mma_bf16(acc[mt][p * 2 + 1], al[mt], bh1);
                }
            }
        }
    }

    // ---- epilogue ----
    const float* biases[3] = {bq, bk, bv};
    float* outs[3] = {g_q, g_k, g_v};
    const int r0 = lane >> 2;
    const int cp = (lane & 3) * 2;
#pragma unroll
    for (int mt = 0; mt < 2; mt++) {
        int gr = row0 + m_warp * 32 + mt * 16 + r0;
#pragma unroll
        for (int nt = 0; nt < 6; nt++) {
            int col = n_warp * 48 + nt * 8 + cp;
            int sel = col >> 6;
            int ci  = col & 63;
            float b0 = biases[sel][ci], b1 = biases[sel][ci + 1];
            if (gr < NN) {
                float2 st = make_float2(acc[mt][nt][0] + b0, acc[mt][nt][1] + b1);
                *(float2*)&outs[sel][(size_t)gr * HD + ci] = st;
            }
            if (gr + 8 < NN) {
                float2 st = make_float2(acc[mt][nt][2] + b0, acc[mt][nt][3] + b1);
                *(float2*)&outs[sel][(size_t)(gr + 8) * HD + ci] = st;
            }
        }
    }
}

// ---------------------------------------------------------------------------
// Pass 1: ex[e] = exp(dot(k[src], q[dest]) / 8); denominator via shared bins.
// 4 edges per warp per iteration (8 lanes x 32B each).
// ---------------------------------------------------------------------------
__global__ __launch_bounds__(512) void edge_pass1(
    const int* __restrict__ ei, const int* __restrict__ batch)
{
    __shared__ float sden[NG];
    const int tid = threadIdx.x;
    if (tid < NG) sden[tid] = 0.f;
    __syncthreads();

    const int lane = tid & 31;
    const int sub = lane >> 3;
    const int sl  = lane & 7;
    const int w = blockIdx.x * 16 + (tid >> 5);
    const int stride = gridDim.x * 16 * 4;

    for (int e0 = w * 4; e0 < NE; e0 += stride) {
        int e = e0 + sub;
        float p = 0.f;
        int s = 0;
        if (e < NE) {
            s = __ldg(&ei[e]);
            int d = __ldg(&ei[NE + e]);
            const float* kr = &g_k[s * HD + sl * 8];
            const float* qr = &g_q[d * HD + sl * 8];
            float4 k0 = *(const float4*)kr;
            float4 k1 = *(const float4*)(kr + 4);
            float4 q0 = *(const float4*)qr;
            float4 q1 = *(const float4*)(qr + 4);
            p = k0.x * q0.x + k0.y * q0.y + k0.z * q0.z + k0.w * q0.w
              + k1.x * q1.x + k1.y * q1.y + k1.z * q1.z + k1.w * q1.w;
        }
#pragma unroll
        for (int o = 4; o > 0; o >>= 1)
            p += __shfl_xor_sync(0xffffffffu, p, o);
        if (sl == 0 && e < NE) {
            float ex = __expf(p * 0.125f);
            g_ex[e] = ex;
            atomicAdd(&sden[__ldg(&batch[s])], ex);
        }
    }
    __syncthreads();
    if (tid < NG) {
        float v = sden[tid];
        if (v != 0.f) atomicAdd(&g_den[tid], v);
    }
}

// ---------------------------------------------------------------------------
__global__ __launch_bounds__(256) void node_inv(const int* __restrict__ batch)
{
    int n = blockIdx.x * 256 + threadIdx.x;
    if (n < NN)
        g_inv[n] = __frcp_rn(g_den[__ldg(&batch[n])] + 1e-6f);
}

// ---------------------------------------------------------------------------
// Pass 2: out[dest] += v[src] * (ex[e] * inv[src]).
// 4 edges per warp as two independent 2-edge groups (16 lanes x 16B each,
// ONE red.v4 per lane) -> 4 chains in flight, unchanged RED pattern.
// ---------------------------------------------------------------------------
__global__ __launch_bounds__(256) void edge_pass2(
    const int* __restrict__ ei, float* __restrict__ out)
{
    const int lane = threadIdx.x & 31;
    const int half = lane >> 4;
    const int hl   = lane & 15;
    const int eb = (blockIdx.x * 8 + (threadIdx.x >> 5)) * 4 + half;

    // Edge group 0: eb ; edge group 1: eb + 2 (both per half-warp)
    int s0 = __ldg(&ei[eb]);
    int d0 = __ldg(&ei[NE + eb]);
    int s1 = __ldg(&ei[eb + 2]);
    int d1 = __ldg(&ei[NE + eb + 2]);

    float a0 = 0.f, a1 = 0.f;
    if (hl == 0) {
        a0 = g_ex[eb]     * g_inv[s0];
        a1 = g_ex[eb + 2] * g_inv[s1];
    }
    a0 = __shfl_sync(0xffffffffu, a0, half << 4);
    a1 = __shfl_sync(0xffffffffu, a1, half << 4);

    float4 v0 = *(const float4*)&g_v[s0 * HD + hl * 4];
    float4 v1 = *(const float4*)&g_v[s1 * HD + hl * 4];

    float* dst0 = &out[d0 * HD + hl * 4];
    float* dst1 = &out[d1 * HD + hl * 4];
    asm volatile("red.global.add.v4.f32 [%0], {%1, %2, %3, %4};"
                 :: "l"(dst0), "f"(v0.x * a0), "f"(v0.y * a0),
                    "f"(v0.z * a0), "f"(v0.w * a0)
                 : "memory");
    asm volatile("red.global.add.v4.f32 [%0], {%1, %2, %3, %4};"
                 :: "l"(dst1), "f"(v1.x * a1), "f"(v1.y * a1),
                    "f"(v1.z * a1), "f"(v1.w * a1)
                 : "memory");
}

// ---------------------------------------------------------------------------
extern "C" void kernel_launch(void* const* d_in, const int* in_sizes, int n_in,
                              void* d_out, int out_size)
{
    const float* x     = (const float*)d_in[0];
    const float* Wq    = (const float*)d_in[1];
    const float* bq    = (const float*)d_in[2];
    const float* Wk    = (const float*)d_in[3];
    const float* bk    = (const float*)d_in[4];
    const float* Wv    = (const float*)d_in[5];
    const float* bv    = (const float*)d_in[6];
    const int*   ei    = (const int*)d_in[7];    // int32 (JAX x64 disabled)
    const int*   batch = (const int*)d_in[8];
    float* out = (float*)d_out;

    cudaFuncSetAttribute(qkv_gemm_hmma,
                         cudaFuncAttributeMaxDynamicSharedMemorySize, SM_TOT);

    wt_build<<<192, 256>>>(Wq, Wk, Wv);                            // 1 (+zero g_den)
    cudaMemsetAsync(d_out, 0, (size_t)out_size * sizeof(float));   // 2
    qkv_gemm_hmma<<<(NN + 63) / 64, 256, SM_TOT>>>(x, bq, bk, bv); // 3
    edge_pass1<<<592, 512>>>(ei, batch);                           // 4
    node_inv<<<(NN + 255) / 256, 256>>>(batch);                    // 5
    edge_pass2<<<NE / 32, 256>>>(ei, out);                         // 6
}

// round 15
// speedup vs baseline: 1.1415x; 1.0158x over previous
#include <cuda_runtime.h>
#include <cuda_bf16.h>
#include <cstdint>

#define NN 50000
#define NE 800000
#define NG 256
#define FIN 256
#define HD 64

__device__ float g_q[NN * HD];
__device__ float g_k[NN * HD];
__device__ float g_v[NN * HD];
__device__ float g_ex[NE];
__device__ float g_den[NG];
__device__ float g_inv[NN];
// W transposed: [n=192][k=256], bf16 hi/lo split
__device__ __nv_bfloat16 g_wth[192 * 256];
__device__ __nv_bfloat16 g_wtl[192 * 256];

// smem layout (dynamic): A hi/lo [64][64] bf16, B hi/lo [192][64] bf16
#define SMA_HI 0
#define SMA_LO 8192
#define SMB_HI 16384
#define SMB_LO (16384 + 24576)
#define SM_TOT (16384 + 49152)   // 64 KB

__device__ __forceinline__ uint32_t smem_u32(const void* p) {
    uint32_t a;
    asm("{ .reg .u64 t; cvta.to.shared.u64 t, %1; cvt.u32.u64 %0, t; }"
        : "=r"(a) : "l"(p));
    return a;
}
__device__ __forceinline__ uint32_t swz(uint32_t row, uint32_t kb) {
    return (row * 128 + kb * 16) ^ ((row & 7) << 4);
}
__device__ __forceinline__ void ldsm_x4(uint32_t* r, uint32_t addr) {
    asm volatile("ldmatrix.sync.aligned.m8n8.x4.shared.b16 {%0,%1,%2,%3}, [%4];"
                 : "=r"(r[0]), "=r"(r[1]), "=r"(r[2]), "=r"(r[3]) : "r"(addr));
}
__device__ __forceinline__ void mma_bf16(float* c, const uint32_t* a,
                                         const uint32_t* b) {
    asm volatile(
        "mma.sync.aligned.m16n8k16.row.col.f32.bf16.bf16.f32 "
        "{%0,%1,%2,%3}, {%4,%5,%6,%7}, {%8,%9}, {%0,%1,%2,%3};"
        : "+f"(c[0]), "+f"(c[1]), "+f"(c[2]), "+f"(c[3])
        : "r"(a[0]), "r"(a[1]), "r"(a[2]), "r"(a[3]), "r"(b[0]), "r"(b[1]));
}
__device__ __forceinline__ uint32_t pack_bf2(float x, float y) {
    __nv_bfloat162 h = {__float2bfloat16(x), __float2bfloat16(y)};
    return *(uint32_t*)&h;
}
__device__ __forceinline__ void cp16(uint32_t dst, const void* src) {
    asm volatile("cp.async.cg.shared.global [%0], [%1], 16;"
                 :: "r"(dst), "l"(__cvta_generic_to_global(src)) : "memory");
}
#define CP_COMMIT() asm volatile("cp.async.commit_group;" ::: "memory")
#define CP_WAIT0()  asm volatile("cp.async.wait_group 0;" ::: "memory")

// ---------------------------------------------------------------------------
// W pre-transpose hi+lo (merged). Block 0 also zeroes g_den.
// ---------------------------------------------------------------------------
__global__ __launch_bounds__(256) void wt_build(
    const float* __restrict__ Wq, const float* __restrict__ Wk,
    const float* __restrict__ Wv)
{
    int n = blockIdx.x;               // 0..191
    int k = threadIdx.x;              // 0..255
    if (n == 0) g_den[k] = 0.f;
    const float* W = (n < 64) ? Wq : (n < 128 ? Wk : Wv);
    float w = W[(size_t)k * HD + (n & 63)];
    __nv_bfloat16 h = __float2bfloat16(w);
    g_wth[n * FIN + k] = h;
    g_wtl[n * FIN + k] = __float2bfloat16(w - __bfloat162float(h));
}

// ---------------------------------------------------------------------------
// Fused QKV GEMM on HMMA bf16x3 (R11 tiling). BM=64, 256 threads / 8 warps
// (2M x 4N), 2 CTAs per SM, K chunked by 64. Staging reordered per chunk:
// A LDG -> B cp.async -> A cvt+STS (hides A latency) -> cp.wait -> BAR.
// ---------------------------------------------------------------------------
__global__ __launch_bounds__(256, 2) void qkv_gemm_hmma(
    const float* __restrict__ x,
    const float* __restrict__ bq, const float* __restrict__ bk,
    const float* __restrict__ bv)
{
    extern __shared__ char smem[];
    const uint32_t sb = smem_u32(smem);
    const int tid = threadIdx.x;
    const int wid = tid >> 5;
    const int lane = tid & 31;
    const int m_warp = wid & 1;       // 2 M groups of 32 rows
    const int n_warp = wid >> 1;      // 4 N groups of 48 cols
    const int row0 = blockIdx.x * 64;

    float acc[2][6][4];
#pragma unroll
    for (int i = 0; i < 2; i++)
#pragma unroll
        for (int j = 0; j < 6; j++)
#pragma unroll
            for (int t = 0; t < 4; t++) acc[i][j][t] = 0.f;

    const int lm_r = lane & 15;
    const int lm_h = lane >> 4;
    // A load coords (fixed): idx = tid + it*256; r = idx>>3, kb = idx&7
    const int ar0 = tid >> 3, akb = tid & 7;

    for (int c = 0; c < 4; c++) {
        __syncthreads();

        // ---- 1) A global loads into registers (long-latency, issue first) ----
        float4 f0[2], f1[2];
#pragma unroll
        for (int it = 0; it < 2; it++) {
            int r = ar0 + it * 32;
            int grow = row0 + r;
            f0[it] = make_float4(0.f, 0.f, 0.f, 0.f);
            f1[it] = f0[it];
            if (grow < NN) {
                const float* src = &x[(size_t)grow * FIN + c * 64 + akb * 8];
                f0[it] = *(const float4*)src;
                f1[it] = *(const float4*)(src + 4);
            }
        }

        // ---- 2) B tiles via cp.async (no register round-trip) ----
#pragma unroll
        for (int it = 0; it < 6; it++) {
            int idx = tid + it * 256;         // 1536 (n,kb) pairs
            int n  = idx >> 3;
            int kb = idx & 7;
            uint32_t off = swz(n, kb);
            cp16(sb + SMB_HI + off, &g_wth[n * FIN + c * 64 + kb * 8]);
            cp16(sb + SMB_LO + off, &g_wtl[n * FIN + c * 64 + kb * 8]);
        }
        CP_COMMIT();

        // ---- 3) A convert + STS (waits on A LDGs; B copies in background) ----
#pragma unroll
        for (int it = 0; it < 2; it++) {
            int r = ar0 + it * 32;
            float fv[8] = {f0[it].x, f0[it].y, f0[it].z, f0[it].w,
                           f1[it].x, f1[it].y, f1[it].z, f1[it].w};
            uint32_t hi[4], lo[4];
#pragma unroll
            for (int j = 0; j < 4; j++) {
                float a = fv[j * 2], b = fv[j * 2 + 1];
                __nv_bfloat16 ha = __float2bfloat16(a);
                __nv_bfloat16 hb = __float2bfloat16(b);
                hi[j] = pack_bf2(a, b);
                lo[j] = pack_bf2(a - __bfloat162float(ha),
                                 b - __bfloat162float(hb));
            }
            uint32_t off = swz(r, akb);
            *(uint4*)(smem + SMA_HI + off) = make_uint4(hi[0], hi[1], hi[2], hi[3]);
            *(uint4*)(smem + SMA_LO + off) = make_uint4(lo[0], lo[1], lo[2], lo[3]);
        }
        CP_WAIT0();
        __syncthreads();

        // ---- compute: 4 k-steps of k16 ----
#pragma unroll
        for (int ks = 0; ks < 4; ks++) {
            uint32_t ah[2][4], al[2][4];
#pragma unroll
            for (int mt = 0; mt < 2; mt++) {
                int r = m_warp * 32 + mt * 16 + lm_r;
                uint32_t o = swz(r, ks * 2 + lm_h);
                ldsm_x4(ah[mt], sb + SMA_HI + o);
                ldsm_x4(al[mt], sb + SMA_LO + o);
            }
#pragma unroll
            for (int p = 0; p < 3; p++) {     // pairs of n-tiles
                int n = n_warp * 48 + p * 16 + lm_r;
                uint32_t o = swz(n, ks * 2 + lm_h);
                uint32_t th[4], tl[4];
                ldsm_x4(th, sb + SMB_HI + o);
                ldsm_x4(tl, sb + SMB_LO + o);
                uint32_t bh0[2] = {th[0], th[2]}, bh1[2] = {th[1], th[3]};
                uint32_t bl0[2] = {tl[0], tl[2]}, bl1[2] = {tl[1], tl[3]};
#pragma unroll
                for (int mt = 0; mt < 2; mt++) {
                    mma_bf16(acc[mt][p * 2], ah[mt], bh0);
                    mma_bf16(acc[mt][p * 2], ah[mt], bl0);
                    mma_bf16(acc[mt][p * 2], al[mt], bh0);
                    mma_bf16(acc[mt][p * 2 + 1], ah[mt], bh1);
                    mma_bf16(acc[mt][p * 2 + 1], ah[mt], bl1);
                    mma_bf16(acc[mt][p * 2 + 1], al[mt], bh1);
                }
            }
        }
    }

    // ---- epilogue ----
    const float* biases[3] = {bq, bk, bv};
    float* outs[3] = {g_q, g_k, g_v};
    const int r0 = lane >> 2;
    const int cp = (lane & 3) * 2;
#pragma unroll
    for (int mt = 0; mt < 2; mt++) {
        int gr = row0 + m_warp * 32 + mt * 16 + r0;
#pragma unroll
        for (int nt = 0; nt < 6; nt++) {
            int col = n_warp * 48 + nt * 8 + cp;
            int sel = col >> 6;
            int ci  = col & 63;
            float b0 = biases[sel][ci], b1 = biases[sel][ci + 1];
            if (gr < NN) {
                float2 st = make_float2(acc[mt][nt][0] + b0, acc[mt][nt][1] + b1);
                *(float2*)&outs[sel][(size_t)gr * HD + ci] = st;
            }
            if (gr + 8 < NN) {
                float2 st = make_float2(acc[mt][nt][2] + b0, acc[mt][nt][3] + b1);
                *(float2*)&outs[sel][(size_t)(gr + 8) * HD + ci] = st;
            }
        }
    }
}

// ---------------------------------------------------------------------------
// Pass 1: ex[e] = exp(dot(k[src], q[dest]) / 8); denominator via shared bins.
// 4 edges per warp per iteration (8 lanes x 32B each).
// ---------------------------------------------------------------------------
__global__ __launch_bounds__(512) void edge_pass1(
    const int* __restrict__ ei, const int* __restrict__ batch)
{
    __shared__ float sden[NG];
    const int tid = threadIdx.x;
    if (tid < NG) sden[tid] = 0.f;
    __syncthreads();

    const int lane = tid & 31;
    const int sub = lane >> 3;
    const int sl  = lane & 7;
    const int w = blockIdx.x * 16 + (tid >> 5);
    const int stride = gridDim.x * 16 * 4;

    for (int e0 = w * 4; e0 < NE; e0 += stride) {
        int e = e0 + sub;
        float p = 0.f;
        int s = 0;
        if (e < NE) {
            s = __ldg(&ei[e]);
            int d = __ldg(&ei[NE + e]);
            const float* kr = &g_k[s * HD + sl * 8];
            const float* qr = &g_q[d * HD + sl * 8];
            float4 k0 = *(const float4*)kr;
            float4 k1 = *(const float4*)(kr + 4);
            float4 q0 = *(const float4*)qr;
            float4 q1 = *(const float4*)(qr + 4);
            p = k0.x * q0.x + k0.y * q0.y + k0.z * q0.z + k0.w * q0.w
              + k1.x * q1.x + k1.y * q1.y + k1.z * q1.z + k1.w * q1.w;
        }
#pragma unroll
        for (int o = 4; o > 0; o >>= 1)
            p += __shfl_xor_sync(0xffffffffu, p, o);
        if (sl == 0 && e < NE) {
            float ex = __expf(p * 0.125f);
            g_ex[e] = ex;
            atomicAdd(&sden[__ldg(&batch[s])], ex);
        }
    }
    __syncthreads();
    if (tid < NG) {
        float v = sden[tid];
        if (v != 0.f) atomicAdd(&g_den[tid], v);
    }
}

// ---------------------------------------------------------------------------
__global__ __launch_bounds__(256) void node_inv(const int* __restrict__ batch)
{
    int n = blockIdx.x * 256 + threadIdx.x;
    if (n < NN)
        g_inv[n] = __frcp_rn(g_den[__ldg(&batch[n])] + 1e-6f);
}

// ---------------------------------------------------------------------------
// Pass 2: out[dest] += v[src] * (ex[e] * inv[src]).
// 4 edges per warp as two independent 2-edge groups (16 lanes x 16B each,
// ONE red.v4 per lane) -> 4 chains in flight, unchanged RED pattern.
// ---------------------------------------------------------------------------
__global__ __launch_bounds__(256) void edge_pass2(
    const int* __restrict__ ei, float* __restrict__ out)
{
    const int lane = threadIdx.x & 31;
    const int half = lane >> 4;
    const int hl   = lane & 15;
    const int eb = (blockIdx.x * 8 + (threadIdx.x >> 5)) * 4 + half;

    int s0 = __ldg(&ei[eb]);
    int d0 = __ldg(&ei[NE + eb]);
    int s1 = __ldg(&ei[eb + 2]);
    int d1 = __ldg(&ei[NE + eb + 2]);

    float a0 = 0.f, a1 = 0.f;
    if (hl == 0) {
        a0 = g_ex[eb]     * g_inv[s0];
        a1 = g_ex[eb + 2] * g_inv[s1];
    }
    a0 = __shfl_sync(0xffffffffu, a0, half << 4);
    a1 = __shfl_sync(0xffffffffu, a1, half << 4);

    float4 v0 = *(const float4*)&g_v[s0 * HD + hl * 4];
    float4 v1 = *(const float4*)&g_v[s1 * HD + hl * 4];

    float* dst0 = &out[d0 * HD + hl * 4];
    float* dst1 = &out[d1 * HD + hl * 4];
    asm volatile("red.global.add.v4.f32 [%0], {%1, %2, %3, %4};"
                 :: "l"(dst0), "f"(v0.x * a0), "f"(v0.y * a0),
                    "f"(v0.z * a0), "f"(v0.w * a0)
                 : "memory");
    asm volatile("red.global.add.v4.f32 [%0], {%1, %2, %3, %4};"
                 :: "l"(dst1), "f"(v1.x * a1), "f"(v1.y * a1),
                    "f"(v1.z * a1), "f"(v1.w * a1)
                 : "memory");
}

// ---------------------------------------------------------------------------
extern "C" void kernel_launch(void* const* d_in, const int* in_sizes, int n_in,
                              void* d_out, int out_size)
{
    const float* x     = (const float*)d_in[0];
    const float* Wq    = (const float*)d_in[1];
    const float* bq    = (const float*)d_in[2];
    const float* Wk    = (const float*)d_in[3];
    const float* bk    = (const float*)d_in[4];
    const float* Wv    = (const float*)d_in[5];
    const float* bv    = (const float*)d_in[6];
    const int*   ei    = (const int*)d_in[7];    // int32 (JAX x64 disabled)
    const int*   batch = (const int*)d_in[8];
    float* out = (float*)d_out;

    cudaFuncSetAttribute(qkv_gemm_hmma,
                         cudaFuncAttributeMaxDynamicSharedMemorySize, SM_TOT);

    wt_build<<<192, 256>>>(Wq, Wk, Wv);                            // 1 (+zero g_den)
    cudaMemsetAsync(d_out, 0, (size_t)out_size * sizeof(float));   // 2
    qkv_gemm_hmma<<<(NN + 63) / 64, 256, SM_TOT>>>(x, bq, bk, bv); // 3 <- ncu(-s5 may shift)
    edge_pass1<<<592, 512>>>(ei, batch);                           // 4
    node_inv<<<(NN + 255) / 256, 256>>>(batch);                    // 5
    edge_pass2<<<NE / 32, 256>>>(ei, out);                         // 6
}